// round 1
// baseline (speedup 1.0000x reference)
#include <cuda_runtime.h>

#define N_NODES 32768
#define F_DIM   128
#define C_CH    4
#define H_HEADS 8
#define D_DIM   32
#define DM      256
#define CHN     32          // C*H
#define E_EDGES 65536
#define B_BRIDGE 8192
#define ET      (E_EDGES + 2*B_BRIDGE)   // 81920

// ---------------- device scratch (static, no allocation) ----------------
__device__ float g_xl[(size_t)N_NODES * DM];          // 33.5 MB
__device__ float g_exps[(size_t)ET * CHN];            // 10.5 MB
__device__ float g_denom[(size_t)N_NODES * CHN];      //  4.2 MB
__device__ float g_pe[C_CH * DM];                     //  4 KB

// ---------------- init: zero denom, compute sinusoidal PE ----------------
__global__ void init_kernel() {
    int gid = blockIdx.x * 256 + threadIdx.x;
    if (gid < N_NODES * CHN) g_denom[gid] = 0.f;
    if (gid < C_CH * DM) {
        int c  = gid >> 8;
        int hd = gid & 255;
        float di  = (float)(hd & ~1);                 // 2*floor(hd/2)
        float div = powf(10000.f, di / 256.f);
        float ang = (float)c / div;
        g_pe[gid] = (hd & 1) ? cosf(ang) : sinf(ang);
    }
}

// ---------------- fused GEMM: xl = x@W_in.T ; out = x@W_res.T + bias -----
// M=32768, K=128, Ncols=1280 (cols [0,256)->g_xl, [256,1280)->d_out)
__global__ __launch_bounds__(256) void gemm_kernel(
    const float* __restrict__ x, const float* __restrict__ W_in,
    const float* __restrict__ W_res, const float* __restrict__ bias,
    float* __restrict__ out)
{
    __shared__ float As[32][132];   // [k][m], padded for vec loads
    __shared__ float Bs[32][68];    // [k][n]
    const int tid = threadIdx.x;
    const int tx = tid & 15, ty = tid >> 4;
    const int m0 = blockIdx.y * 128;
    const int n0 = blockIdx.x * 64;
    float acc[8][4];
    #pragma unroll
    for (int i = 0; i < 8; i++)
        #pragma unroll
        for (int j = 0; j < 4; j++) acc[i][j] = 0.f;

    for (int kb = 0; kb < 128; kb += 32) {
        #pragma unroll
        for (int r = 0; r < 4; r++) {
            int li  = tid + r * 256;          // 1024 float4 of A tile
            int row = li >> 3;
            int kc  = (li & 7) << 2;
            float4 av = *(const float4*)(x + (size_t)(m0 + row) * 128 + kb + kc);
            As[kc  ][row] = av.x; As[kc+1][row] = av.y;
            As[kc+2][row] = av.z; As[kc+3][row] = av.w;
        }
        #pragma unroll
        for (int r = 0; r < 2; r++) {
            int li = tid + r * 256;           // 512 float4 of B tile
            int j  = li >> 3;
            int kc = (li & 7) << 2;
            int jg = n0 + j;
            const float* wrow = (jg < 256) ? (W_in  + (size_t)jg * 128)
                                           : (W_res + (size_t)(jg - 256) * 128);
            float4 bv = *(const float4*)(wrow + kb + kc);
            Bs[kc  ][j] = bv.x; Bs[kc+1][j] = bv.y;
            Bs[kc+2][j] = bv.z; Bs[kc+3][j] = bv.w;
        }
        __syncthreads();
        #pragma unroll
        for (int k = 0; k < 32; k++) {
            float4 a0 = *(const float4*)&As[k][ty * 8];
            float4 a1 = *(const float4*)&As[k][ty * 8 + 4];
            float4 b  = *(const float4*)&Bs[k][tx * 4];
            float a[8] = {a0.x, a0.y, a0.z, a0.w, a1.x, a1.y, a1.z, a1.w};
            float bb[4] = {b.x, b.y, b.z, b.w};
            #pragma unroll
            for (int i = 0; i < 8; i++)
                #pragma unroll
                for (int j = 0; j < 4; j++)
                    acc[i][j] = fmaf(a[i], bb[j], acc[i][j]);
        }
        __syncthreads();
    }
    const int n = n0 + tx * 4;
    #pragma unroll
    for (int i = 0; i < 8; i++) {
        int m = m0 + ty * 8 + i;
        float4 v = make_float4(acc[i][0], acc[i][1], acc[i][2], acc[i][3]);
        if (n < 256) {
            *(float4*)(g_xl + (size_t)m * 256 + n) = v;
        } else {
            const float4 bb = *(const float4*)(bias + (n - 256));
            v.x += bb.x; v.y += bb.y; v.z += bb.z; v.w += bb.w;
            *(float4*)(out + (size_t)m * 1024 + (n - 256)) = v;
        }
    }
}

// ---------------- scores + denom: one warp per edge ----------------------
__global__ __launch_bounds__(256) void scores_kernel(
    const int* __restrict__ edge_index, const int* __restrict__ bridge_index,
    const float* __restrict__ double_attn)
{
    __shared__ float pe_s[1024];
    __shared__ float aw_s[1024];
    for (int i = threadIdx.x; i < 1024; i += 256) {
        pe_s[i] = g_pe[i];
        aw_s[i] = double_attn[i];
    }
    __syncthreads();
    const int e    = (blockIdx.x * 256 + threadIdx.x) >> 5;
    const int lane = threadIdx.x & 31;

    int u, v, dst, type;
    if (e < E_EDGES)                { u = edge_index[e];   v = edge_index[E_EDGES + e];   dst = v; type = 0; }
    else if (e < E_EDGES + B_BRIDGE){ int i = e - E_EDGES;            u = bridge_index[i]; v = bridge_index[B_BRIDGE + i]; dst = v; type = 1; }
    else                            { int i = e - E_EDGES - B_BRIDGE; u = bridge_index[i]; v = bridge_index[B_BRIDGE + i]; dst = u; type = 2; }

    const float* xu = g_xl + (size_t)u * DM;
    const float* xv = g_xl + (size_t)v * DM;
    float S[8];
    #pragma unroll
    for (int h = 0; h < 8; h++) S[h] = xu[h * 32 + lane] + xv[h * 32 + lane];

    float myscore = 0.f;
    #pragma unroll
    for (int ch = 0; ch < 32; ch++) {
        const int c = ch >> 3, h = ch & 7;
        int c2;
        if (type == 0)      c2 = c;
        else if (type == 1) c2 = (c < 3) ? c + 1 : 3;
        else                c2 = (c > 0) ? c - 1 : 0;
        float t = S[h] + pe_s[c * 256 + h * 32 + lane] + pe_s[c2 * 256 + h * 32 + lane];
        t = (t >= 0.f) ? t : 0.2f * t;                       // leaky(0.2)
        bool masked = (type == 1 && c == 3) || (type == 2 && c == 0);
        float prod = masked ? 0.f : t * aw_s[ch * 32 + lane];
        #pragma unroll
        for (int off = 16; off; off >>= 1)
            prod += __shfl_xor_sync(0xffffffffu, prod, off);
        if (lane == ch) myscore = prod;
    }
    float ex = expf(myscore);   // global-max shift omitted: alpha-invariant (eps ~1e-16)
    g_exps[(size_t)e * 32 + lane] = ex;
    atomicAdd(&g_denom[(size_t)dst * 32 + lane], ex);
}

// ---------------- scatter: proj accumulation via vectorized red ----------
__device__ __forceinline__ void red_add_v4(float* p, float4 v) {
    asm volatile("red.global.add.v4.f32 [%0], {%1,%2,%3,%4};"
                 :: "l"(p), "f"(v.x), "f"(v.y), "f"(v.z), "f"(v.w) : "memory");
}

__global__ __launch_bounds__(256) void scatter_kernel(
    const int* __restrict__ edge_index, const int* __restrict__ bridge_index,
    float* __restrict__ out)
{
    __shared__ __align__(16) float pe_s[1024];
    for (int i = threadIdx.x; i < 1024; i += 256) pe_s[i] = g_pe[i];
    __syncthreads();
    const int e    = (blockIdx.x * 256 + threadIdx.x) >> 5;
    const int lane = threadIdx.x & 31;

    int fs, dst;
    if (e < E_EDGES)                 { fs = edge_index[e];              dst = edge_index[E_EDGES + e]; }
    else if (e < E_EDGES + B_BRIDGE) { int i = e - E_EDGES;             fs = bridge_index[i];            dst = bridge_index[B_BRIDGE + i]; }
    else                             { int i = e - E_EDGES - B_BRIDGE;  fs = bridge_index[B_BRIDGE + i]; dst = bridge_index[i]; }

    // faithful reference bug: x_src[full_src[e]] == xr[edge_index[0][full_src[e]]]
    const int s2 = edge_index[fs];

    float a = g_exps[(size_t)e * 32 + lane] /
              (g_denom[(size_t)dst * 32 + lane] + 1e-16f);

    const float4* xs = (const float4*)(g_xl + (size_t)s2 * DM);
    const int q = lane & 7;          // which float4 within a head row
    const int g = lane >> 3;         // chain index c for this lane group
    float4 xv[8];
    #pragma unroll
    for (int h = 0; h < 8; h++) xv[h] = xs[h * 8 + q];

    float* ob = out + (size_t)dst * 1024;
    #pragma unroll
    for (int it = 0; it < 8; it++) {     // it = head h (static reg index)
        const int ch = g * 8 + it;       // c = g, h = it
        float ach = __shfl_sync(0xffffffffu, a, ch);
        float4 p = *(const float4*)(pe_s + g * 256 + it * 32 + q * 4);
        float4 vv;
        vv.x = (xv[it].x + p.x) * ach;
        vv.y = (xv[it].y + p.y) * ach;
        vv.z = (xv[it].z + p.z) * ach;
        vv.w = (xv[it].w + p.w) * ach;
        red_add_v4(ob + ch * 32 + q * 4, vv);
    }
}

// ---------------- final PReLU -------------------------------------------
__global__ void prelu_kernel(float* __restrict__ out, const float* __restrict__ pw) {
    const float w = pw[0];
    size_t i = ((size_t)blockIdx.x * 256 + threadIdx.x) * 4;
    float4 v = *(float4*)(out + i);
    v.x = (v.x >= 0.f) ? v.x : w * v.x;
    v.y = (v.y >= 0.f) ? v.y : w * v.y;
    v.z = (v.z >= 0.f) ? v.z : w * v.z;
    v.w = (v.w >= 0.f) ? v.w : w * v.w;
    *(float4*)(out + i) = v;
}

// ---------------- launch --------------------------------------------------
extern "C" void kernel_launch(void* const* d_in, const int* in_sizes, int n_in,
                              void* d_out, int out_size) {
    const float* x            = (const float*)d_in[0];
    const int*   edge_index   = (const int*)  d_in[1];
    const int*   bridge_index = (const int*)  d_in[2];
    const float* W_in         = (const float*)d_in[3];
    const float* double_attn  = (const float*)d_in[4];
    const float* W_res        = (const float*)d_in[5];
    const float* bias         = (const float*)d_in[6];
    const float* prelu_w      = (const float*)d_in[7];
    float* out = (float*)d_out;

    init_kernel<<<4096, 256>>>();                                 // 1M threads
    gemm_kernel<<<dim3(20, 256), 256>>>(x, W_in, W_res, bias, out);
    scores_kernel<<<ET / 8, 256>>>(edge_index, bridge_index, double_attn);
    scatter_kernel<<<ET / 8, 256>>>(edge_index, bridge_index, out);
    prelu_kernel<<<(N_NODES * 1024) / (256 * 4), 256>>>(out, prelu_w);
}